// round 11
// baseline (speedup 1.0000x reference)
#include <cuda_runtime.h>
#include <cuda_bf16.h>
#include <cuda_fp16.h>
#include <cstdint>

// ---------------- problem constants ----------------
constexpr int Bb   = 8;
constexpr int Ll   = 2048;
constexpr int Tt   = Bb * Ll;      // 16384 tokens
constexpr int Dd   = 512;
constexpr int Kk   = 4096;
constexpr int QN   = Tt * Dd;      // 8388608
constexpr int LOSS_OFF = QN;
constexpr int IDX_OFF  = QN + 1;

#define DECAYF 0.99f
#define EPSF   1e-5f
#define MARGIN 1.0f

// ---------------- device scratch (static, no runtime alloc) ----------------
__device__ float g_c2[Kk];
__device__ float g_x2[Tt];
__device__ int   g_idx[Tt];
__device__ float g_counts[Kk];
__device__ float g_avgc[Kk];
__device__ float g_dw[(size_t)Kk * Dd];
__device__ float g_cbnew[(size_t)Kk * Dd];
__device__ float g_N;
__device__ float g_loss;
__device__ unsigned short g_Sh[(size_t)Tt * Kk];  // fp16 approx scores (128 MB)
__device__ float g_partS[32][Tt];                 // per-yblock row minima
__device__ unsigned short g_xh[(size_t)Tt * Dd];  // fp16 x
__device__ unsigned short g_cbh[(size_t)Kk * Dd]; // fp16 codebook

// ---------------- helpers ----------------
__device__ __forceinline__ uint32_t smem_u32(const void* p) {
    uint32_t a;
    asm("{ .reg .u64 t; cvta.to.shared.u64 t, %1; cvt.u32.u64 %0, t; }" : "=r"(a) : "l"(p));
    return a;
}
#define SMEM_SWIZZLE_128B(o) ((o) ^ (((o) >> 3) & 0x70))

#define CP_ASYNC16(sm, gp) \
    asm volatile("cp.async.cg.shared.global [%0], [%1], 16;" :: "r"(sm), "l"(gp))
#define CP_COMMIT() asm volatile("cp.async.commit_group;" ::: "memory")
#define CP_WAIT1()  asm volatile("cp.async.wait_group 1;" ::: "memory")
#define CP_WAIT0()  asm volatile("cp.async.wait_group 0;" ::: "memory")

__device__ __forceinline__ void ldmatrix_x4(uint32_t& r0, uint32_t& r1,
                                            uint32_t& r2, uint32_t& r3, uint32_t addr) {
    asm volatile("ldmatrix.sync.aligned.m8n8.x4.shared.b16 {%0,%1,%2,%3}, [%4];"
        : "=r"(r0), "=r"(r1), "=r"(r2), "=r"(r3) : "r"(addr));
}
__device__ __forceinline__ void mma_f16(float* c, const uint32_t* a, uint32_t b0, uint32_t b1) {
    asm volatile("mma.sync.aligned.m16n8k16.row.col.f32.f16.f16.f32 "
        "{%0,%1,%2,%3}, {%4,%5,%6,%7}, {%8,%9}, {%0,%1,%2,%3};"
        : "+f"(c[0]), "+f"(c[1]), "+f"(c[2]), "+f"(c[3])
        : "r"(a[0]), "r"(a[1]), "r"(a[2]), "r"(a[3]), "r"(b0), "r"(b1));
}

// ---------------- K0: zero scratch ----------------
__global__ void k_zero() {
    int gid = blockIdx.x * blockDim.x + threadIdx.x;
    int stride = gridDim.x * blockDim.x;
    int n = Kk * Dd;
    for (int i = gid; i < n; i += stride) g_dw[i] = 0.f;
    for (int i = gid; i < Kk; i += stride) g_counts[i] = 0.f;
    if (gid == 0) { g_N = 0.f; g_loss = 0.f; }
}

// ---------------- fp16 converts ----------------
__global__ void k_cvtx(const float* __restrict__ s) {
    int i = blockIdx.x * blockDim.x + threadIdx.x;
    if (i >= QN) return;
    __half h = __float2half_rn(__ldg(s + i));
    g_xh[i] = *(unsigned short*)&h;
}
__global__ void k_cvtc(const float* __restrict__ s) {
    int i = blockIdx.x * blockDim.x + threadIdx.x;
    if (i >= Kk * Dd) return;
    __half h = __float2half_rn(__ldg(s + i));
    g_cbh[i] = *(unsigned short*)&h;
}

// ---------------- K1: c2 / x2 ----------------
__global__ void k_c2(const float* __restrict__ cb) {
    int w = (blockIdx.x * blockDim.x + threadIdx.x) >> 5;
    int lane = threadIdx.x & 31;
    if (w >= Kk) return;
    const float4* row = (const float4*)(cb + (size_t)w * Dd);
    float s = 0.f;
    #pragma unroll
    for (int i = lane; i < Dd / 4; i += 32) {
        float4 v = __ldg(row + i);
        s += v.x * v.x + v.y * v.y + v.z * v.z + v.w * v.w;
    }
    #pragma unroll
    for (int o = 16; o; o >>= 1) s += __shfl_xor_sync(0xffffffffu, s, o);
    if (lane == 0) g_c2[w] = s;
}
__global__ void k_x2(const float* __restrict__ x) {
    int w = (blockIdx.x * blockDim.x + threadIdx.x) >> 5;
    int lane = threadIdx.x & 31;
    if (w >= Tt) return;
    const float4* row = (const float4*)(x + (size_t)w * Dd);
    float s = 0.f;
    #pragma unroll
    for (int i = lane; i < Dd / 4; i += 32) {
        float4 v = __ldg(row + i);
        s += v.x * v.x + v.y * v.y + v.z * v.z + v.w * v.w;
    }
    #pragma unroll
    for (int o = 16; o; o >>= 1) s += __shfl_xor_sync(0xffffffffu, s, o);
    if (lane == 0) g_x2[w] = s;
}

// ---------------- K2: HMMA fp16 GEMM -> fp16 scores + partial row-min ----------------
// 128x128 tile, 8 warps (2x4), warp 64x32, m16n8k16, KC=64, cp.async 2-stage.
constexpr int GM = 128, GN = 128, GKC = 64;
constexpr int GSTAGES = Dd / GKC;            // 8
constexpr int SOFF_A  = 0;                   // 2 x 16KB
constexpr int SOFF_B  = 32768;               // 2 x 16KB
constexpr int SOFF_C2 = 65536;               // 512B floats
constexpr int SMEM_G  = 66048;
constexpr int SSTR    = 136;                 // fp16 score staging stride (halves)

__global__ __launch_bounds__(256, 2)
void k_gemm(const unsigned short* __restrict__ xh, const unsigned short* __restrict__ cbh) {
    extern __shared__ __align__(1024) char smem[];
    const uint32_t sb = smem_u32(smem);
    const int tid = threadIdx.x, wid = tid >> 5, lane = tid & 31;
    const int tb = blockIdx.x * GM;
    const int kbase = blockIdx.y * GN;
    const int wr = (wid >> 2) * 64;           // warp row base
    const int wc = (wid & 3) * 32;            // warp col base
    const int gid = lane >> 2, tig = lane & 3;

    float* c2s = (float*)(smem + SOFF_C2);
    if (tid < 32) *((float4*)c2s + tid) = __ldg((const float4*)(g_c2 + kbase) + tid);

    float acc[4][4][4];
    #pragma unroll
    for (int ma = 0; ma < 4; ma++)
        #pragma unroll
        for (int na = 0; na < 4; na++)
            #pragma unroll
            for (int q = 0; q < 4; q++) acc[ma][na][q] = 0.f;

    // per-thread gmem->smem mapping: 4 chunks of 16B each for A and B
    auto issue = [&](int s, int buf) {
        uint32_t ab = sb + SOFF_A + buf * 16384;
        uint32_t bb = sb + SOFF_B + buf * 16384;
        #pragma unroll
        for (int i = 0; i < 4; i++) {
            int id = tid + 256 * i;
            int row = id >> 3, ch = id & 7;
            uint32_t off = SMEM_SWIZZLE_128B((uint32_t)(row * 128 + ch * 16));
            const unsigned short* ga = xh  + (size_t)(tb + row) * Dd + s * GKC + ch * 8;
            const unsigned short* gb = cbh + (size_t)(kbase + row) * Dd + s * GKC + ch * 8;
            CP_ASYNC16(ab + off, ga);
            CP_ASYNC16(bb + off, gb);
        }
    };

    issue(0, 0); CP_COMMIT();
    issue(1, 1); CP_COMMIT();

    for (int s = 0; s < GSTAGES; ++s) {
        if (s == GSTAGES - 1) { CP_WAIT0(); } else { CP_WAIT1(); }
        __syncthreads();
        int buf = s & 1;
        uint32_t ab = sb + SOFF_A + buf * 16384;
        uint32_t bb = sb + SOFF_B + buf * 16384;
        #pragma unroll
        for (int ks = 0; ks < 4; ks++) {
            uint32_t a[4][4], b[2][4];
            #pragma unroll
            for (int ma = 0; ma < 4; ma++) {
                uint32_t row = wr + ma * 16 + (lane & 15);
                uint32_t col = ks * 32 + (lane >> 4) * 16;
                ldmatrix_x4(a[ma][0], a[ma][1], a[ma][2], a[ma][3],
                            ab + SMEM_SWIZZLE_128B(row * 128 + col));
            }
            #pragma unroll
            for (int j = 0; j < 2; j++) {
                uint32_t row = wc + j * 16 + (lane & 7) + ((lane >> 4) << 3);
                uint32_t col = ks * 32 + (((lane >> 3) & 1) << 4);
                ldmatrix_x4(b[j][0], b[j][1], b[j][2], b[j][3],
                            bb + SMEM_SWIZZLE_128B(row * 128 + col));
            }
            #pragma unroll
            for (int ma = 0; ma < 4; ma++)
                #pragma unroll
                for (int na = 0; na < 4; na++) {
                    int j = na >> 1, h = (na & 1) * 2;
                    mma_f16(acc[ma][na], a[ma], b[j][h], b[j][h + 1]);
                }
        }
        __syncthreads();
        if (s + 2 < GSTAGES) { issue(s + 2, buf); CP_COMMIT(); }
    }

    // ---- epilogue: score = c2 - 2*acc -> fp16 smem staging ----
    __half* Ssm = (__half*)smem;          // [128][SSTR]
    #pragma unroll
    for (int ma = 0; ma < 4; ma++) {
        #pragma unroll
        for (int na = 0; na < 4; na++) {
            int row = wr + ma * 16 + gid;
            int col = wc + na * 8 + tig * 2;
            float c2a = c2s[col], c2b = c2s[col + 1];
            __half2 h0 = __floats2half2_rn(c2a - 2.f * acc[ma][na][0],
                                           c2b - 2.f * acc[ma][na][1]);
            __half2 h1 = __floats2half2_rn(c2a - 2.f * acc[ma][na][2],
                                           c2b - 2.f * acc[ma][na][3]);
            *(__half2*)&Ssm[row * SSTR + col]       = h0;
            *(__half2*)&Ssm[(row + 8) * SSTR + col] = h1;
        }
    }
    __syncthreads();

    // ---- dump coalesced + per-row min ----
    #pragma unroll
    for (int i = 0; i < 16; i++) {
        int r = wid * 16 + i;
        uint2 v = *(const uint2*)&Ssm[r * SSTR + lane * 4];
        float2 f0 = __half22float2(*(__half2*)&v.x);
        float2 f1 = __half22float2(*(__half2*)&v.y);
        float m = fminf(fminf(f0.x, f0.y), fminf(f1.x, f1.y));
        #pragma unroll
        for (int o = 16; o; o >>= 1) m = fminf(m, __shfl_xor_sync(0xffffffffu, m, o));
        *(uint2*)(g_Sh + (size_t)(tb + r) * Kk + kbase + lane * 4) = v;
        if (lane == 0) g_partS[blockIdx.y][tb + r] = m;
    }
}

// ---------------- K3: threshold + exact rescoring argmin ----------------
__global__ __launch_bounds__(256)
void k_argmin(const float* __restrict__ x, const float* __restrict__ cb,
              float* __restrict__ out) {
    int wid = threadIdx.x >> 5, lane = threadIdx.x & 31;
    int t = blockIdx.x * 8 + wid;
    if (t >= Tt) return;

    float m = g_partS[lane][t];
    #pragma unroll
    for (int o = 16; o; o >>= 1) m = fminf(m, __shfl_xor_sync(0xffffffffu, m, o));
    float thr = m + MARGIN;

    // preload x row (lane covers floats [lane*16, lane*16+16))
    float4 xv[4];
    #pragma unroll
    for (int i = 0; i < 4; i++)
        xv[i] = __ldg((const float4*)(x + (size_t)t * Dd) + lane * 4 + i);
    float x2t = g_x2[t];

    const uint4* Srow = (const uint4*)(g_Sh + (size_t)t * Kk);
    float best = 3.4e38f;
    int bidx = 0x7fffffff;

    for (int c = 0; c < 16; c++) {
        uint4 v = __ldg(Srow + c * 32 + lane);
        uint32_t w[4] = {v.x, v.y, v.z, v.w};
        bool has = false;
        #pragma unroll
        for (int q = 0; q < 4; q++) {
            float2 ff = __half22float2(*(__half2*)&w[q]);
            has = has || (ff.x <= thr) || (ff.y <= thr);
        }
        unsigned bal = __ballot_sync(0xffffffffu, has);
        while (bal) {
            int src = __ffs(bal) - 1;
            bal &= bal - 1;
            uint32_t sv[4];
            #pragma unroll
            for (int q = 0; q < 4; q++) sv[q] = __shfl_sync(0xffffffffu, w[q], src);
            #pragma unroll
            for (int q = 0; q < 4; q++) {
                float2 ff = __half22float2(*(__half2*)&sv[q]);
                float fs[2] = {ff.x, ff.y};
                #pragma unroll
                for (int e = 0; e < 2; e++) {
                    if (fs[e] <= thr) {
                        int k = (c * 32 + src) * 8 + q * 2 + e;
                        // exact fp32 dot with reference-grid rounding
                        const float4* crow = (const float4*)(cb + (size_t)k * Dd);
                        float p = 0.f;
                        #pragma unroll
                        for (int i = 0; i < 4; i++) {
                            float4 cv = __ldg(crow + lane * 4 + i);
                            p = fmaf(xv[i].x, cv.x, p);
                            p = fmaf(xv[i].y, cv.y, p);
                            p = fmaf(xv[i].z, cv.z, p);
                            p = fmaf(xv[i].w, cv.w, p);
                        }
                        #pragma unroll
                        for (int o = 16; o; o >>= 1) p += __shfl_xor_sync(0xffffffffu, p, o);
                        float d2 = __fadd_rn(__fsub_rn(x2t, __fmul_rn(2.f, p)), __ldg(g_c2 + k));
                        if (d2 < best || (d2 == best && k < bidx)) { best = d2; bidx = k; }
                    }
                }
            }
        }
    }
    if (lane == 0) {
        g_idx[t] = bidx;
        out[IDX_OFF + t] = (float)bidx;
        atomicAdd(&g_counts[bidx], 1.0f);
    }
}

// ---------------- K4: dw scatter-add ----------------
__global__ void k_scatter(const float* __restrict__ x) {
    int n = Tt * (Dd / 4);
    for (int wi = blockIdx.x * blockDim.x + threadIdx.x; wi < n; wi += gridDim.x * blockDim.x) {
        int t = wi >> 7, dq = wi & 127;
        int idx = g_idx[t];
        float4 v = __ldg((const float4*)(x + (size_t)t * Dd) + dq);
        float* dst = g_dw + (size_t)idx * Dd + dq * 4;
        atomicAdd(dst + 0, v.x);
        atomicAdd(dst + 1, v.y);
        atomicAdd(dst + 2, v.z);
        atomicAdd(dst + 3, v.w);
    }
}

// ---------------- K5: EMA cluster + N reduce ----------------
__global__ void k_ema(const float* __restrict__ hc, const float* __restrict__ cnt) {
    int k = blockIdx.x * blockDim.x + threadIdx.x;
    if (k >= Kk) return;
    float count = __ldg(cnt);
    float bias = 1.f - powf(DECAYF, count + 1.f);
    float hcn = __ldg(hc + k) * DECAYF + (1.0f - DECAYF) * g_counts[k];
    float avg = hcn / bias;
    g_avgc[k] = avg;
    float s = avg;
    #pragma unroll
    for (int o = 16; o; o >>= 1) s += __shfl_xor_sync(0xffffffffu, s, o);
    if ((threadIdx.x & 31) == 0) atomicAdd(&g_N, s);
}

// ---------------- K6: codebook_new ----------------
__global__ void k_cbnew(const float* __restrict__ hdw, const float* __restrict__ cnt) {
    int n = Kk * (Dd / 4);
    int i = blockIdx.x * blockDim.x + threadIdx.x;
    if (i >= n) return;
    float count = __ldg(cnt);
    float bias = 1.f - powf(DECAYF, count + 1.f);
    float N = g_N;
    int k = i >> 7;
    float cc = (g_avgc[k] + EPSF) / (N + (float)Kk * EPSF) * N;
    float inv = 1.f / (bias * cc);
    float4 h = __ldg((const float4*)hdw + i);
    float4 w = *(((const float4*)g_dw) + i);
    float4 o;
    o.x = (h.x * DECAYF + (1.0f - DECAYF) * w.x) * inv;
    o.y = (h.y * DECAYF + (1.0f - DECAYF) * w.y) * inv;
    o.z = (h.z * DECAYF + (1.0f - DECAYF) * w.z) * inv;
    o.w = (h.w * DECAYF + (1.0f - DECAYF) * w.w) * inv;
    ((float4*)g_cbnew)[i] = o;
}

// ---------------- K7: gather quantized + loss ----------------
__global__ void k_quant(const float* __restrict__ x, float* __restrict__ out) {
    int n = Tt * (Dd / 4);
    float lsum = 0.f;
    for (int wi = blockIdx.x * blockDim.x + threadIdx.x; wi < n; wi += gridDim.x * blockDim.x) {
        int t = wi >> 7, dq = wi & 127;
        int idx = g_idx[t];
        float4 q  = *(((const float4*)(g_cbnew + (size_t)idx * Dd)) + dq);
        float4 xv = __ldg(((const float4*)x) + wi);
        float4 o;
        o.x = __fadd_rn(xv.x, __fsub_rn(q.x, xv.x));
        o.y = __fadd_rn(xv.y, __fsub_rn(q.y, xv.y));
        o.z = __fadd_rn(xv.z, __fsub_rn(q.z, xv.z));
        o.w = __fadd_rn(xv.w, __fsub_rn(q.w, xv.w));
        ((float4*)out)[wi] = o;
        float a = __fsub_rn(xv.x, o.x), b = __fsub_rn(xv.y, o.y);
        float c = __fsub_rn(xv.z, o.z), d = __fsub_rn(xv.w, o.w);
        lsum += a * a + b * b + c * c + d * d;
    }
    #pragma unroll
    for (int o = 16; o; o >>= 1) lsum += __shfl_xor_sync(0xffffffffu, lsum, o);
    __shared__ float red[8];
    int wid = threadIdx.x >> 5, lane = threadIdx.x & 31;
    if (lane == 0) red[wid] = lsum;
    __syncthreads();
    if (threadIdx.x == 0) {
        float s = 0.f;
        #pragma unroll
        for (int i = 0; i < 8; i++) s += red[i];
        atomicAdd(&g_loss, s);
    }
}

// ---------------- K8: finalize loss ----------------
__global__ void k_fin(float* __restrict__ out) {
    out[LOSS_OFF] = 0.5f * g_loss / (float)QN;
}

// ---------------- launch ----------------
extern "C" void kernel_launch(void* const* d_in, const int* in_sizes, int n_in,
                              void* d_out, int out_size) {
    const float* x   = (const float*)d_in[0];
    const float* cb  = (const float*)d_in[1];
    const float* hc  = (const float*)d_in[2];
    const float* hdw = (const float*)d_in[3];
    const float* cnt = (const float*)d_in[4];
    float* out = (float*)d_out;

    k_zero<<<2048, 256>>>();
    k_cvtx<<<QN / 256, 256>>>(x);
    k_cvtc<<<(Kk * Dd) / 256, 256>>>(cb);
    k_c2<<<(Kk * 32) / 256, 256>>>(cb);
    k_x2<<<(Tt * 32) / 256, 256>>>(x);

    cudaFuncSetAttribute(k_gemm, cudaFuncAttributeMaxDynamicSharedMemorySize, SMEM_G);
    {
        dim3 grid(Tt / GM, Kk / GN);    // (128, 32)
        k_gemm<<<grid, 256, SMEM_G>>>(g_xh, g_cbh);
    }
    k_argmin<<<Tt / 8, 256>>>(x, cb, out);
    k_scatter<<<2048, 256>>>(x);
    k_ema<<<Kk / 256, 256>>>(hc, cnt);
    k_cbnew<<<(Kk * Dd / 4) / 256, 256>>>(hdw, cnt);
    k_quant<<<1024, 256>>>(x, out);
    k_fin<<<1, 1>>>(out);
}

// round 12
// speedup vs baseline: 1.3071x; 1.3071x over previous
#include <cuda_runtime.h>
#include <cstdint>

// ---------------- problem constants ----------------
constexpr int Bb   = 8;
constexpr int Ll   = 2048;
constexpr int Tt   = Bb * Ll;      // 16384 tokens
constexpr int Dd   = 512;
constexpr int Kk   = 4096;
constexpr int QN   = Tt * Dd;      // 8388608
constexpr int LOSS_OFF = QN;       // scalar loss position
constexpr int IDX_OFF  = QN + 1;   // indices (as float) position

#define DECAYF 0.99f
#define EPSF   1e-5f

// ---------------- device scratch (no allocation allowed) ----------------
__device__ float g_c2[Kk];
__device__ float g_x2[Tt];
__device__ float g_partS[2][Tt];
__device__ int   g_partI[2][Tt];
__device__ int   g_idx[Tt];
__device__ float g_counts[Kk];
__device__ float g_avgc[Kk];
__device__ float g_dw[(size_t)Kk * Dd];
__device__ float g_cbnew[(size_t)Kk * Dd];
__device__ float g_N;
__device__ float g_loss;
__device__ float g_xT[(size_t)Dd * Tt];   // x transposed [D][T]
__device__ float g_cT[(size_t)Dd * Kk];   // codebook transposed [D][K]

// ---------------- f32x2 helpers (Blackwell packed fp32) ----------------
__device__ __forceinline__ unsigned long long pack2(float lo, float hi) {
    unsigned long long r;
    asm("mov.b64 %0, {%1, %2};" : "=l"(r) : "f"(lo), "f"(hi));
    return r;
}
__device__ __forceinline__ void unpack2(unsigned long long v, float& lo, float& hi) {
    asm("mov.b64 {%0, %1}, %2;" : "=f"(lo), "=f"(hi) : "l"(v));
}
__device__ __forceinline__ void ffma2(unsigned long long& d, unsigned long long a, unsigned long long b) {
    asm("fma.rn.f32x2 %0, %1, %2, %3;" : "=l"(d) : "l"(a), "l"(b), "l"(d));
}
__device__ __forceinline__ uint32_t smem_u32(const void* p) {
    uint32_t a;
    asm("{ .reg .u64 t; cvta.to.shared.u64 t, %1; cvt.u32.u64 %0, t; }" : "=r"(a) : "l"(p));
    return a;
}
#define CP_ASYNC16(sm, gp) \
    asm volatile("cp.async.cg.shared.global [%0], [%1], 16;" :: "r"(sm), "l"(gp))
#define CP_COMMIT() asm volatile("cp.async.commit_group;" ::: "memory")
#define CP_WAIT1()  asm volatile("cp.async.wait_group 1;" ::: "memory")
#define CP_WAIT0()  asm volatile("cp.async.wait_group 0;" ::: "memory")

// ---------------- K0: zero scratch ----------------
__global__ void k_zero() {
    int gid = blockIdx.x * blockDim.x + threadIdx.x;
    int stride = gridDim.x * blockDim.x;
    int n = Kk * Dd;
    for (int i = gid; i < n; i += stride) g_dw[i] = 0.f;
    for (int i = gid; i < Kk; i += stride) g_counts[i] = 0.f;
    if (gid == 0) { g_N = 0.f; g_loss = 0.f; }
}

// ---------------- K0b: 32x32 tiled transpose (out[c][r] = in[r][c]) ----------------
__global__ void k_tr(const float* __restrict__ in, float* __restrict__ out, int R, int C) {
    __shared__ float t[32][33];
    int cb = blockIdx.x * 32, rb = blockIdx.y * 32;
    int tx = threadIdx.x, ty = threadIdx.y;
    #pragma unroll
    for (int j = 0; j < 32; j += 8)
        t[ty + j][tx] = __ldg(in + (size_t)(rb + ty + j) * C + cb + tx);
    __syncthreads();
    #pragma unroll
    for (int j = 0; j < 32; j += 8)
        out[(size_t)(cb + ty + j) * R + rb + tx] = t[tx][ty + j];
}

// ---------------- K1: c2[k] = ||codebook[k]||^2 ----------------
__global__ void k_c2(const float* __restrict__ cb) {
    int w = (blockIdx.x * blockDim.x + threadIdx.x) >> 5;
    int lane = threadIdx.x & 31;
    if (w >= Kk) return;
    const float4* row = (const float4*)(cb + (size_t)w * Dd);
    float s = 0.f;
    #pragma unroll
    for (int i = lane; i < Dd / 4; i += 32) {
        float4 v = __ldg(row + i);
        s += v.x * v.x + v.y * v.y + v.z * v.z + v.w * v.w;
    }
    #pragma unroll
    for (int o = 16; o; o >>= 1) s += __shfl_xor_sync(0xffffffffu, s, o);
    if (lane == 0) g_c2[w] = s;
}

// ---------------- K1b: x2[t] = ||x[t]||^2 ----------------
__global__ void k_x2(const float* __restrict__ x) {
    int w = (blockIdx.x * blockDim.x + threadIdx.x) >> 5;
    int lane = threadIdx.x & 31;
    if (w >= Tt) return;
    const float4* row = (const float4*)(x + (size_t)w * Dd);
    float s = 0.f;
    #pragma unroll
    for (int i = lane; i < Dd / 4; i += 32) {
        float4 v = __ldg(row + i);
        s += v.x * v.x + v.y * v.y + v.z * v.z + v.w * v.w;
    }
    #pragma unroll
    for (int o = 16; o; o >>= 1) s += __shfl_xor_sync(0xffffffffu, s, o);
    if (lane == 0) g_x2[w] = s;
}

// ---------------- K2: fused distance GEMM + partial argmin ----------------
// 256 threads, TM=128 tokens x TN=128 codes, KC=16, K split in 2 (gridDim.y).
// Inputs pre-transposed to [D][*] so each stage tile loads via cp.async.cg 16B
// (k-rows contiguous): no LDG->reg->STS staging, freeing registers so ptxas can
// pipeline the LDS->FFMA2 chains.
// d2 = rn(rn(x2 - rn(2*xc)) + c2)  -- matches reference fp32 rounding grid.
constexpr int TM = 128, TN = 128, KC = 16, KSPLIT = 2;
constexpr int KHALF  = Kk / KSPLIT;       // 2048 codes per block
constexpr int SSTRIDE = 132;              // 16B-multiple row stride, pad kills conflicts

__global__ __launch_bounds__(256, 2)
void k_dist(const float* __restrict__ xT, const float* __restrict__ cT) {
    __shared__ float Xs[2][KC][SSTRIDE];
    __shared__ float Cs[2][KC][SSTRIDE];

    const int tid = threadIdx.x;
    const int ty = tid >> 4;          // 0..15  -> token groups
    const int tx = tid & 15;          // 0..15  -> code groups
    const int tb = blockIdx.x * TM;   // token tile base
    const int kb0 = blockIdx.y * KHALF;

    const uint32_t xsb = smem_u32(&Xs[0][0][0]);
    const uint32_t csb = smem_u32(&Cs[0][0][0]);

    float best[8];
    int   bidx[8];
    #pragma unroll
    for (int i = 0; i < 8; i++) { best[i] = 3.4e38f; bidx[i] = 0; }

    // x2 for the 8 tokens this thread owns (slot i -> local token tl)
    float x2s[8];
    #pragma unroll
    for (int i = 0; i < 8; i++) {
        int p = i >> 1, e = i & 1;
        int tl = (p < 2) ? (ty * 4 + p * 2 + e) : (64 + ty * 4 + (p - 2) * 2 + e);
        x2s[i] = g_x2[tb + tl];
    }

    unsigned long long acc[4][8];     // [token-pair][code], f32x2

    auto issue = [&](int s) {
        int kt = s >> 5;              // ktile (32 KC-chunks each)
        int dc = s & 31;
        int db = dc * KC;
        int kb = kb0 + kt * TN;
        int buf = s & 1;
        #pragma unroll
        for (int i = 0; i < 2; i++) {
            int f = tid + 256 * i;
            int col = (f & 31) * 4;   // 0..124 step 4
            int kq  = f >> 5;         // 0..15
            uint32_t soff = (uint32_t)(((buf * KC + kq) * SSTRIDE + col) * 4);
            CP_ASYNC16(xsb + soff, xT + (size_t)(db + kq) * Tt + tb + col);
            CP_ASYNC16(csb + soff, cT + (size_t)(db + kq) * Kk + kb + col);
        }
        CP_COMMIT();
    };

    constexpr int NSTG = (KHALF / TN) * (Dd / KC);  // 16 * 32 = 512 stages
    issue(0);
    issue(1);

    for (int s = 0; s < NSTG; ++s) {
        if (s == NSTG - 1) { CP_WAIT0(); } else { CP_WAIT1(); }
        __syncthreads();
        int buf = s & 1;

        if ((s & 31) == 0) {
            #pragma unroll
            for (int p = 0; p < 4; p++)
                #pragma unroll
                for (int j = 0; j < 8; j++) acc[p][j] = 0ull;
        }

        #pragma unroll
        for (int kk = 0; kk < KC; kk++) {
            ulonglong2 xA = *(const ulonglong2*)&Xs[buf][kk][ty * 4];
            ulonglong2 xB = *(const ulonglong2*)&Xs[buf][kk][64 + ty * 4];
            float4 cA = *(const float4*)&Cs[buf][kk][tx * 4];
            float4 cB = *(const float4*)&Cs[buf][kk][64 + tx * 4];
            float cv[8] = {cA.x, cA.y, cA.z, cA.w, cB.x, cB.y, cB.z, cB.w};
            #pragma unroll
            for (int j = 0; j < 8; j++) {
                unsigned long long cj = pack2(cv[j], cv[j]);
                ffma2(acc[0][j], xA.x, cj);
                ffma2(acc[1][j], xA.y, cj);
                ffma2(acc[2][j], xB.x, cj);
                ffma2(acc[3][j], xB.y, cj);
            }
        }

        if ((s & 31) == 31) {                       // ktile epilogue
            int kt = s >> 5;
            int kb = kb0 + kt * TN;
            float4 c2a = __ldg((const float4*)(g_c2 + kb + tx * 4));
            float4 c2b = __ldg((const float4*)(g_c2 + kb + 64 + tx * 4));
            float c2v[8] = {c2a.x, c2a.y, c2a.z, c2a.w, c2b.x, c2b.y, c2b.z, c2b.w};
            #pragma unroll
            for (int j = 0; j < 8; j++) {
                int code = kb + ((j < 4) ? (tx * 4 + j) : (64 + tx * 4 + (j - 4)));
                #pragma unroll
                for (int p = 0; p < 4; p++) {
                    float lo, hi;
                    unpack2(acc[p][j], lo, hi);
                    int i0 = p * 2;     // best[] slot for lo
                    // d2 = rn(rn(x2 - rn(2*xc)) + c2)  -- match reference rounding
                    float s0 = __fadd_rn(__fsub_rn(x2s[i0],     __fmul_rn(2.0f, lo)), c2v[j]);
                    float s1 = __fadd_rn(__fsub_rn(x2s[i0 + 1], __fmul_rn(2.0f, hi)), c2v[j]);
                    if (s0 < best[i0])     { best[i0]     = s0; bidx[i0]     = code; }
                    if (s1 < best[i0 + 1]) { best[i0 + 1] = s1; bidx[i0 + 1] = code; }
                }
            }
        }

        __syncthreads();
        if (s + 2 < NSTG) issue(s + 2);
    }

    // cross-thread (tx) reduction; overlay reduction arrays on the tile buffers
    __syncthreads();
    float* rS = &Xs[0][0][0];          // 128*16 floats = 2048 fits easily
    int*   rI = (int*)&Cs[0][0][0];
    #pragma unroll
    for (int i = 0; i < 8; i++) {
        int p = i >> 1, e = i & 1;
        int tl = (p < 2) ? (ty * 4 + p * 2 + e) : (64 + ty * 4 + (p - 2) * 2 + e);
        rS[tl * 16 + tx] = best[i];
        rI[tl * 16 + tx] = bidx[i];
    }
    __syncthreads();
    if (tid < TM) {
        float bs = rS[tid * 16];
        int   bi = rI[tid * 16];
        #pragma unroll
        for (int j = 1; j < 16; j++) {
            float s2 = rS[tid * 16 + j];
            int   i2 = rI[tid * 16 + j];
            if (s2 < bs || (s2 == bs && i2 < bi)) { bs = s2; bi = i2; }
        }
        g_partS[blockIdx.y][tb + tid] = bs;
        g_partI[blockIdx.y][tb + tid] = bi;
    }
}

// ---------------- K2b: merge K-split partials, counts, indices out ----------------
__global__ void k_merge(float* __restrict__ outF) {
    int t = blockIdx.x * blockDim.x + threadIdx.x;
    if (t >= Tt) return;
    float s0 = g_partS[0][t], s1 = g_partS[1][t];
    int   i0 = g_partI[0][t], i1 = g_partI[1][t];
    int bi = (s1 < s0) ? i1 : i0;   // tie -> i0 (lower index), matches jnp.argmin
    g_idx[t] = bi;
    outF[IDX_OFF + t] = (float)bi;
    atomicAdd(&g_counts[bi], 1.0f);
}

// ---------------- K3: dw scatter-add ----------------
__global__ void k_scatter(const float* __restrict__ x) {
    int n = Tt * (Dd / 4);
    for (int wi = blockIdx.x * blockDim.x + threadIdx.x; wi < n; wi += gridDim.x * blockDim.x) {
        int t = wi >> 7, dq = wi & 127;
        int idx = g_idx[t];
        float4 v = __ldg((const float4*)(x + (size_t)t * Dd) + dq);
        float* dst = g_dw + (size_t)idx * Dd + dq * 4;
        atomicAdd(dst + 0, v.x);
        atomicAdd(dst + 1, v.y);
        atomicAdd(dst + 2, v.z);
        atomicAdd(dst + 3, v.w);
    }
}

// ---------------- K4: EMA cluster + N reduce ----------------
__global__ void k_ema(const float* __restrict__ hc, const float* __restrict__ cnt) {
    int k = blockIdx.x * blockDim.x + threadIdx.x;
    if (k >= Kk) return;
    float count = __ldg(cnt);
    float bias = 1.f - powf(DECAYF, count + 1.f);
    float hcn = __ldg(hc + k) * DECAYF + (1.0f - DECAYF) * g_counts[k];
    float avg = hcn / bias;
    g_avgc[k] = avg;
    float s = avg;
    #pragma unroll
    for (int o = 16; o; o >>= 1) s += __shfl_xor_sync(0xffffffffu, s, o);
    if ((threadIdx.x & 31) == 0) atomicAdd(&g_N, s);
}

// ---------------- K5: codebook_new ----------------
__global__ void k_cbnew(const float* __restrict__ hdw, const float* __restrict__ cnt) {
    int n = Kk * (Dd / 4);
    int i = blockIdx.x * blockDim.x + threadIdx.x;
    if (i >= n) return;
    float count = __ldg(cnt);
    float bias = 1.f - powf(DECAYF, count + 1.f);
    float N = g_N;
    int k = i >> 7;
    float cc = (g_avgc[k] + EPSF) / (N + (float)Kk * EPSF) * N;
    float inv = 1.f / (bias * cc);
    float4 h = __ldg((const float4*)hdw + i);
    float4 w = *(((const float4*)g_dw) + i);
    float4 o;
    o.x = (h.x * DECAYF + (1.0f - DECAYF) * w.x) * inv;
    o.y = (h.y * DECAYF + (1.0f - DECAYF) * w.y) * inv;
    o.z = (h.z * DECAYF + (1.0f - DECAYF) * w.z) * inv;
    o.w = (h.w * DECAYF + (1.0f - DECAYF) * w.w) * inv;
    ((float4*)g_cbnew)[i] = o;
}

// ---------------- K6: gather quantized + loss ----------------
__global__ void k_quant(const float* __restrict__ x, float* __restrict__ out) {
    int n = Tt * (Dd / 4);
    float lsum = 0.f;
    for (int wi = blockIdx.x * blockDim.x + threadIdx.x; wi < n; wi += gridDim.x * blockDim.x) {
        int t = wi >> 7, dq = wi & 127;
        int idx = g_idx[t];
        float4 q  = *(((const float4*)(g_cbnew + (size_t)idx * Dd)) + dq);
        float4 xv = __ldg(((const float4*)x) + wi);
        float4 o;
        o.x = __fadd_rn(xv.x, __fsub_rn(q.x, xv.x));
        o.y = __fadd_rn(xv.y, __fsub_rn(q.y, xv.y));
        o.z = __fadd_rn(xv.z, __fsub_rn(q.z, xv.z));
        o.w = __fadd_rn(xv.w, __fsub_rn(q.w, xv.w));
        ((float4*)out)[wi] = o;
        float a = __fsub_rn(xv.x, o.x), b = __fsub_rn(xv.y, o.y);
        float c = __fsub_rn(xv.z, o.z), d = __fsub_rn(xv.w, o.w);
        lsum += a * a + b * b + c * c + d * d;
    }
    #pragma unroll
    for (int o = 16; o; o >>= 1) lsum += __shfl_xor_sync(0xffffffffu, lsum, o);
    __shared__ float red[8];
    int wid = threadIdx.x >> 5, lane = threadIdx.x & 31;
    if (lane == 0) red[wid] = lsum;
    __syncthreads();
    if (threadIdx.x == 0) {
        float s = 0.f;
        #pragma unroll
        for (int i = 0; i < 8; i++) s += red[i];
        atomicAdd(&g_loss, s);
    }
}

// ---------------- K7: finalize loss ----------------
__global__ void k_fin(float* __restrict__ out) {
    out[LOSS_OFF] = 0.5f * g_loss / (float)QN;
}

// ---------------- launch ----------------
extern "C" void kernel_launch(void* const* d_in, const int* in_sizes, int n_in,
                              void* d_out, int out_size) {
    const float* x   = (const float*)d_in[0];
    const float* cb  = (const float*)d_in[1];
    const float* hc  = (const float*)d_in[2];
    const float* hdw = (const float*)d_in[3];
    const float* cnt = (const float*)d_in[4];
    float* out = (float*)d_out;

    k_zero<<<2048, 256>>>();
    {
        dim3 blk(32, 8);
        k_tr<<<dim3(Dd / 32, Tt / 32), blk>>>(x,  g_xT, Tt, Dd);
        k_tr<<<dim3(Dd / 32, Kk / 32), blk>>>(cb, g_cT, Kk, Dd);
    }
    k_c2<<<(Kk * 32) / 256, 256>>>(cb);                 // warp per code row
    k_x2<<<(Tt * 32) / 256, 256>>>(x);                  // warp per token row
    {
        dim3 grid(Tt / TM, KSPLIT);                      // (128, 2)
        k_dist<<<grid, 256>>>(g_xT, g_cT);
    }
    k_merge<<<Tt / 256, 256>>>(out);
    k_scatter<<<2048, 256>>>(x);
    k_ema<<<Kk / 256, 256>>>(hc, cnt);
    k_cbnew<<<(Kk * Dd / 4) / 256, 256>>>(hdw, cnt);
    k_quant<<<1024, 256>>>(x, out);
    k_fin<<<1, 1>>>(out);
}

// round 14
// speedup vs baseline: 13.9953x; 10.7070x over previous
#include <cuda_runtime.h>
#include <cstdint>

// ---------------- problem constants ----------------
constexpr int Bb   = 8;
constexpr int Ll   = 2048;
constexpr int Tt   = Bb * Ll;      // 16384 tokens
constexpr int Dd   = 512;
constexpr int Kk   = 4096;
constexpr int QN   = Tt * Dd;      // 8388608
constexpr int LOSS_OFF = QN;       // scalar loss position
constexpr int IDX_OFF  = QN + 1;   // indices (as float) position

#define DECAYF 0.99f
#define EPSF   1e-5f

constexpr int KSPLIT = 4;

// ---------------- device scratch (no allocation allowed) ----------------
__device__ float g_c2[Kk];
__device__ float g_x2[Tt];
__device__ float g_partS[KSPLIT][Tt];
__device__ int   g_partI[KSPLIT][Tt];
__device__ int   g_idx[Tt];
__device__ float g_counts[Kk];
__device__ float g_avgc[Kk];
__device__ float g_dw[(size_t)Kk * Dd];
__device__ float g_cbnew[(size_t)Kk * Dd];
__device__ float g_N;
__device__ float g_loss;

// ---------------- f32x2 helpers (Blackwell packed fp32) ----------------
__device__ __forceinline__ unsigned long long pack2(float lo, float hi) {
    unsigned long long r;
    asm("mov.b64 %0, {%1, %2};" : "=l"(r) : "f"(lo), "f"(hi));
    return r;
}
__device__ __forceinline__ void unpack2(unsigned long long v, float& lo, float& hi) {
    asm("mov.b64 {%0, %1}, %2;" : "=f"(lo), "=f"(hi) : "l"(v));
}
__device__ __forceinline__ void ffma2(unsigned long long& d, unsigned long long a, unsigned long long b) {
    asm("fma.rn.f32x2 %0, %1, %2, %3;" : "=l"(d) : "l"(a), "l"(b), "l"(d));
}

// ---------------- K0: zero scratch ----------------
__global__ void k_zero() {
    int gid = blockIdx.x * blockDim.x + threadIdx.x;
    int stride = gridDim.x * blockDim.x;
    int n = Kk * Dd;
    for (int i = gid; i < n; i += stride) g_dw[i] = 0.f;
    for (int i = gid; i < Kk; i += stride) g_counts[i] = 0.f;
    if (gid == 0) { g_N = 0.f; g_loss = 0.f; }
}

// ---------------- K1: c2[k] = ||codebook[k]||^2 ----------------
__global__ void k_c2(const float* __restrict__ cb) {
    int w = (blockIdx.x * blockDim.x + threadIdx.x) >> 5;
    int lane = threadIdx.x & 31;
    if (w >= Kk) return;
    const float4* row = (const float4*)(cb + (size_t)w * Dd);
    float s = 0.f;
    #pragma unroll
    for (int i = lane; i < Dd / 4; i += 32) {
        float4 v = __ldg(row + i);
        s += v.x * v.x + v.y * v.y + v.z * v.z + v.w * v.w;
    }
    #pragma unroll
    for (int o = 16; o; o >>= 1) s += __shfl_xor_sync(0xffffffffu, s, o);
    if (lane == 0) g_c2[w] = s;
}

// ---------------- K1b: x2[t] = ||x[t]||^2 ----------------
__global__ void k_x2(const float* __restrict__ x) {
    int w = (blockIdx.x * blockDim.x + threadIdx.x) >> 5;
    int lane = threadIdx.x & 31;
    if (w >= Tt) return;
    const float4* row = (const float4*)(x + (size_t)w * Dd);
    float s = 0.f;
    #pragma unroll
    for (int i = lane; i < Dd / 4; i += 32) {
        float4 v = __ldg(row + i);
        s += v.x * v.x + v.y * v.y + v.z * v.z + v.w * v.w;
    }
    #pragma unroll
    for (int o = 16; o; o >>= 1) s += __shfl_xor_sync(0xffffffffu, s, o);
    if (lane == 0) g_x2[w] = s;
}

// ---------------- K2: fused distance GEMM + partial argmin ----------------
// 256 threads, TM=128 tokens x TN=128 codes, KC=16, K split in 4 (gridDim.y).
// d2 = rn(rn(x2 - rn(2*xc)) + c2) matches the reference's fp32 rounding grid.
constexpr int TM = 128, TN = 128, KC = 16;
constexpr int KHALF  = Kk / KSPLIT;       // 1024 codes per block
constexpr int SSTRIDE = TN + 4;           // 132 floats, 16B-multiple, pad kills conflicts

__global__ __launch_bounds__(256, 2)
void k_dist(const float* __restrict__ x, const float* __restrict__ cb) {
    __shared__ float Xs[2][KC][SSTRIDE];
    __shared__ float Cs[2][KC][SSTRIDE];

    const int tid = threadIdx.x;
    const int ty = tid >> 4;          // 0..15  -> token groups
    const int tx = tid & 15;          // 0..15  -> code groups
    const int tb = blockIdx.x * TM;   // token tile base
    const int kb0 = blockIdx.y * KHALF;

    float4 xr[2], cr[2];              // staging registers

    float best[8];
    int   bidx[8];
    #pragma unroll
    for (int i = 0; i < 8; i++) { best[i] = 3.4e38f; bidx[i] = 0; }

    // x2 for the 8 tokens this thread owns (slot i -> local token tl)
    float x2s[8];
    #pragma unroll
    for (int i = 0; i < 8; i++) {
        int p = i >> 1, e = i & 1;
        int tl = (p < 2) ? (ty * 4 + p * 2 + e) : (64 + ty * 4 + (p - 2) * 2 + e);
        x2s[i] = g_x2[tb + tl];
    }

    unsigned long long acc[4][8];     // [token-pair][code], f32x2

    auto ldStage = [&](int s) {
        int kt = s >> 5;              // ktile (32 dchunks each)
        int dc = s & 31;
        int db = dc * KC;
        int kb = kb0 + kt * TN;
        #pragma unroll
        for (int i = 0; i < 2; i++) {
            int f = tid + 256 * i;
            int col = f & 127;
            int kq  = f >> 7;         // 0..3 (float4 within KC=16)
            xr[i] = __ldg((const float4*)(x  + (size_t)(tb + col) * Dd + db + kq * 4));
            cr[i] = __ldg((const float4*)(cb + (size_t)(kb + col) * Dd + db + kq * 4));
        }
    };
    auto stStage = [&](int buf) {
        #pragma unroll
        for (int i = 0; i < 2; i++) {
            int f = tid + 256 * i;
            int col = f & 127;
            int kq  = f >> 7;
            Xs[buf][kq * 4 + 0][col] = xr[i].x;
            Xs[buf][kq * 4 + 1][col] = xr[i].y;
            Xs[buf][kq * 4 + 2][col] = xr[i].z;
            Xs[buf][kq * 4 + 3][col] = xr[i].w;
            Cs[buf][kq * 4 + 0][col] = cr[i].x;
            Cs[buf][kq * 4 + 1][col] = cr[i].y;
            Cs[buf][kq * 4 + 2][col] = cr[i].z;
            Cs[buf][kq * 4 + 3][col] = cr[i].w;
        }
    };

    constexpr int NSTG = (KHALF / TN) * (Dd / KC);  // 8 * 32 = 256 stages
    ldStage(0);

    for (int s = 0; s < NSTG; ++s) {
        int buf = s & 1;
        stStage(buf);
        if (s + 1 < NSTG) ldStage(s + 1);
        __syncthreads();

        if ((s & 31) == 0) {
            #pragma unroll
            for (int p = 0; p < 4; p++)
                #pragma unroll
                for (int j = 0; j < 8; j++) acc[p][j] = 0ull;
        }

        #pragma unroll
        for (int kk = 0; kk < KC; kk++) {
            ulonglong2 xA = *(const ulonglong2*)&Xs[buf][kk][ty * 4];
            ulonglong2 xB = *(const ulonglong2*)&Xs[buf][kk][64 + ty * 4];
            float4 cA = *(const float4*)&Cs[buf][kk][tx * 4];
            float4 cB = *(const float4*)&Cs[buf][kk][64 + tx * 4];
            float cv[8] = {cA.x, cA.y, cA.z, cA.w, cB.x, cB.y, cB.z, cB.w};
            #pragma unroll
            for (int j = 0; j < 8; j++) {
                unsigned long long cj = pack2(cv[j], cv[j]);
                ffma2(acc[0][j], xA.x, cj);
                ffma2(acc[1][j], xA.y, cj);
                ffma2(acc[2][j], xB.x, cj);
                ffma2(acc[3][j], xB.y, cj);
            }
        }

        if ((s & 31) == 31) {                       // ktile epilogue
            int kt = s >> 5;
            int kb = kb0 + kt * TN;
            float4 c2a = __ldg((const float4*)(g_c2 + kb + tx * 4));
            float4 c2b = __ldg((const float4*)(g_c2 + kb + 64 + tx * 4));
            float c2v[8] = {c2a.x, c2a.y, c2a.z, c2a.w, c2b.x, c2b.y, c2b.z, c2b.w};
            #pragma unroll
            for (int j = 0; j < 8; j++) {
                int code = kb + ((j < 4) ? (tx * 4 + j) : (64 + tx * 4 + (j - 4)));
                #pragma unroll
                for (int p = 0; p < 4; p++) {
                    float lo, hi;
                    unpack2(acc[p][j], lo, hi);
                    int i0 = p * 2;     // best[] slot for lo
                    // d2 = rn(rn(x2 - rn(2*xc)) + c2)  -- match reference rounding
                    float s0 = __fadd_rn(__fsub_rn(x2s[i0],     __fmul_rn(2.0f, lo)), c2v[j]);
                    float s1 = __fadd_rn(__fsub_rn(x2s[i0 + 1], __fmul_rn(2.0f, hi)), c2v[j]);
                    if (s0 < best[i0])     { best[i0]     = s0; bidx[i0]     = code; }
                    if (s1 < best[i0 + 1]) { best[i0 + 1] = s1; bidx[i0 + 1] = code; }
                }
            }
        }
    }

    // cross-thread (tx) reduction; overlay reduction arrays on the tile buffers
    __syncthreads();
    float* rS = &Xs[0][0][0];          // 128*16 floats = 2048 <= available
    int*   rI = (int*)&Cs[0][0][0];
    #pragma unroll
    for (int i = 0; i < 8; i++) {
        int p = i >> 1, e = i & 1;
        int tl = (p < 2) ? (ty * 4 + p * 2 + e) : (64 + ty * 4 + (p - 2) * 2 + e);
        rS[tl * 16 + tx] = best[i];
        rI[tl * 16 + tx] = bidx[i];
    }
    __syncthreads();
    if (tid < TM) {
        float bs = rS[tid * 16];
        int   bi = rI[tid * 16];
        #pragma unroll
        for (int j = 1; j < 16; j++) {
            float s2 = rS[tid * 16 + j];
            int   i2 = rI[tid * 16 + j];
            if (s2 < bs || (s2 == bs && i2 < bi)) { bs = s2; bi = i2; }
        }
        g_partS[blockIdx.y][tb + tid] = bs;
        g_partI[blockIdx.y][tb + tid] = bi;
    }
}

// ---------------- K2b: merge K-split partials, counts, indices out ----------------
__global__ void k_merge(float* __restrict__ outF) {
    int t = blockIdx.x * blockDim.x + threadIdx.x;
    if (t >= Tt) return;
    // scan splits in ascending code order; strict < keeps the lowest index on
    // ties, matching jnp.argmin
    float bs = g_partS[0][t];
    int   bi = g_partI[0][t];
    #pragma unroll
    for (int j = 1; j < KSPLIT; j++) {
        float s = g_partS[j][t];
        int   i = g_partI[j][t];
        if (s < bs) { bs = s; bi = i; }
    }
    g_idx[t] = bi;
    outF[IDX_OFF + t] = (float)bi;
    atomicAdd(&g_counts[bi], 1.0f);
}

// ---------------- K3: dw scatter-add ----------------
__global__ void k_scatter(const float* __restrict__ x) {
    int n = Tt * (Dd / 4);
    for (int wi = blockIdx.x * blockDim.x + threadIdx.x; wi < n; wi += gridDim.x * blockDim.x) {
        int t = wi >> 7, dq = wi & 127;
        int idx = g_idx[t];
        float4 v = __ldg((const float4*)(x + (size_t)t * Dd) + dq);
        float* dst = g_dw + (size_t)idx * Dd + dq * 4;
        atomicAdd(dst + 0, v.x);
        atomicAdd(dst + 1, v.y);
        atomicAdd(dst + 2, v.z);
        atomicAdd(dst + 3, v.w);
    }
}

// ---------------- K4: EMA cluster + N reduce ----------------
__global__ void k_ema(const float* __restrict__ hc, const float* __restrict__ cnt) {
    int k = blockIdx.x * blockDim.x + threadIdx.x;
    if (k >= Kk) return;
    float count = __ldg(cnt);
    float bias = 1.f - powf(DECAYF, count + 1.f);
    float hcn = __ldg(hc + k) * DECAYF + (1.0f - DECAYF) * g_counts[k];
    float avg = hcn / bias;
    g_avgc[k] = avg;
    float s = avg;
    #pragma unroll
    for (int o = 16; o; o >>= 1) s += __shfl_xor_sync(0xffffffffu, s, o);
    if ((threadIdx.x & 31) == 0) atomicAdd(&g_N, s);
}

// ---------------- K5: codebook_new ----------------
__global__ void k_cbnew(const float* __restrict__ hdw, const float* __restrict__ cnt) {
    int n = Kk * (Dd / 4);
    int i = blockIdx.x * blockDim.x + threadIdx.x;
    if (i >= n) return;
    float count = __ldg(cnt);
    float bias = 1.f - powf(DECAYF, count + 1.f);
    float N = g_N;
    int k = i >> 7;
    float cc = (g_avgc[k] + EPSF) / (N + (float)Kk * EPSF) * N;
    float inv = 1.f / (bias * cc);
    float4 h = __ldg((const float4*)hdw + i);
    float4 w = *(((const float4*)g_dw) + i);
    float4 o;
    o.x = (h.x * DECAYF + (1.0f - DECAYF) * w.x) * inv;
    o.y = (h.y * DECAYF + (1.0f - DECAYF) * w.y) * inv;
    o.z = (h.z * DECAYF + (1.0f - DECAYF) * w.z) * inv;
    o.w = (h.w * DECAYF + (1.0f - DECAYF) * w.w) * inv;
    ((float4*)g_cbnew)[i] = o;
}

// ---------------- K6: gather quantized + loss ----------------
__global__ void k_quant(const float* __restrict__ x, float* __restrict__ out) {
    int n = Tt * (Dd / 4);
    float lsum = 0.f;
    for (int wi = blockIdx.x * blockDim.x + threadIdx.x; wi < n; wi += gridDim.x * blockDim.x) {
        int t = wi >> 7, dq = wi & 127;
        int idx = g_idx[t];
        float4 q  = *(((const float4*)(g_cbnew + (size_t)idx * Dd)) + dq);
        float4 xv = __ldg(((const float4*)x) + wi);
        float4 o;
        o.x = __fadd_rn(xv.x, __fsub_rn(q.x, xv.x));
        o.y = __fadd_rn(xv.y, __fsub_rn(q.y, xv.y));
        o.z = __fadd_rn(xv.z, __fsub_rn(q.z, xv.z));
        o.w = __fadd_rn(xv.w, __fsub_rn(q.w, xv.w));
        ((float4*)out)[wi] = o;
        float a = __fsub_rn(xv.x, o.x), b = __fsub_rn(xv.y, o.y);
        float c = __fsub_rn(xv.z, o.z), d = __fsub_rn(xv.w, o.w);
        lsum += a * a + b * b + c * c + d * d;
    }
    #pragma unroll
    for (int o = 16; o; o >>= 1) lsum += __shfl_xor_sync(0xffffffffu, lsum, o);
    __shared__ float red[8];
    int wid = threadIdx.x >> 5, lane = threadIdx.x & 31;
    if (lane == 0) red[wid] = lsum;
    __syncthreads();
    if (threadIdx.x == 0) {
        float s = 0.f;
        #pragma unroll
        for (int i = 0; i < 8; i++) s += red[i];
        atomicAdd(&g_loss, s);
    }
}

// ---------------- K7: finalize loss ----------------
__global__ void k_fin(float* __restrict__ out) {
    out[LOSS_OFF] = 0.5f * g_loss / (float)QN;
}

// ---------------- launch ----------------
extern "C" void kernel_launch(void* const* d_in, const int* in_sizes, int n_in,
                              void* d_out, int out_size) {
    const float* x   = (const float*)d_in[0];
    const float* cb  = (const float*)d_in[1];
    const float* hc  = (const float*)d_in[2];
    const float* hdw = (const float*)d_in[3];
    const float* cnt = (const float*)d_in[4];
    float* out = (float*)d_out;

    k_zero<<<2048, 256>>>();
    k_c2<<<(Kk * 32) / 256, 256>>>(cb);                 // warp per code row
    k_x2<<<(Tt * 32) / 256, 256>>>(x);                  // warp per token row
    {
        dim3 grid(Tt / TM, KSPLIT);                      // (128, 4) = 512 blocks
        k_dist<<<grid, 256>>>(x, cb);
    }
    k_merge<<<Tt / 256, 256>>>(out);
    k_scatter<<<2048, 256>>>(x);
    k_ema<<<Kk / 256, 256>>>(hc, cnt);
    k_cbnew<<<(Kk * Dd / 4) / 256, 256>>>(hdw, cnt);
    k_quant<<<1024, 256>>>(x, out);
    k_fin<<<1, 1>>>(out);
}